// round 7
// baseline (speedup 1.0000x reference)
#include <cuda_runtime.h>

// GARCH(1,1): h[t] = (omega + alpha*r[t-1]^2) + beta*h[t-1], h[0] = var(r, ddof=1)
// out[0..n) = sqrt(h), out[n..2n) = h
//
// Hybrid design:
//   Phase 1 (per block): stage r[tile-256 .. tile+8192) into smem with bulk
//     independent float4 LDGs (high MLP); fp32 variance partials ride along.
//   Phase 2 (per warp): each warp produces a 1024-output span from smem,
//     in 256-elem segments (8 consecutive elems/lane):
//       2x LDS.128 + 1 scalar LDS -> drivers -> 7-FMA chain ->
//       5-step Kogge-Stone shuffle scan (multipliers beta^(8*2^k)) ->
//       carry apply -> sqrt.approx -> STG.128 from registers.
//   beta<1 => contractive: 256-elem warm-up halo per warp (shared via smem,
//   only 3% extra DRAM reads per block); cross-segment carry keeps the
//   beta^(8*lane) exact term, drops the beta^256 one (~8e-19).
//   True h[t] = h_hat[t] + beta^t*h0 (linearity); h0 only matters for t<~100,
//   patched by the last block to finish (ticket), which also reduces variance.

#define TPB    256
#define WARPS  8
#define WSPAN  1024              // outputs per warp
#define BOUT   (WARPS*WSPAN)     // 8192 outputs per block-tile
#define HALO   256
#define SMEMN  (BOUT + HALO)     // 8448 staged floats
#define TSEG   (1 + WSPAN/256)   // 5 segments: 1 halo + 4 output
#define FIXN   256
#define MAXB   2048

__device__ double   g_psum[MAXB];
__device__ double   g_psumsq[MAXB];
__device__ unsigned g_ticket = 0;

__device__ __forceinline__ float fsqrt_ap(float x) {
    float y; asm("sqrt.approx.f32 %0, %1;" : "=f"(y) : "f"(x)); return y;
}

__global__ void __launch_bounds__(TPB)
garch_fused(const float* __restrict__ r,
            const float* __restrict__ omega_p,
            const float* __restrict__ alpha_p,
            const float* __restrict__ beta_p,
            float* __restrict__ out,
            int n, int ntiles, int write_h)
{
    __shared__ __align__(16) float sbuf[SMEMN];
    __shared__ float    swsum[WARPS], swq[WARPS];
    __shared__ unsigned s_ticket;
    __shared__ float    sh0;

    const int tid  = threadIdx.x;
    const int wid  = tid >> 5;
    const int lane = tid & 31;
    const unsigned FULL = 0xFFFFFFFFu;

    const float omega = *omega_p;
    const float alpha = *alpha_p;
    const float beta  = *beta_p;

    const float b2 = beta * beta, b4 = b2 * b2;
    const float M0 = b4 * b4;          // beta^8
    const float M1 = M0 * M0;          // beta^16
    const float M2 = M1 * M1;          // beta^32
    const float M3 = M2 * M2;          // beta^64
    const float M4 = M3 * M3;          // beta^128

    float lanepow = 1.0f;              // beta^(8*lane)
    { float p = M0; int e = lane;
      while (e) { if (e & 1) lanepow *= p; p *= p; e >>= 1; } }

    const bool wh  = (write_h != 0);
    const bool wh4 = wh && ((n & 3) == 0);

    float vs = 0.0f, vq = 0.0f;

    for (int bb = blockIdx.x; bb < ntiles; bb += gridDim.x) {
        const int base_t = bb * BOUT - HALO;      // global index of sbuf[0]

        // ---- Phase 1: bulk stage into smem (exclusive region + halo) ----
        #pragma unroll
        for (int j = 0; j < BOUT / 4 / TPB; ++j) {        // 8 iterations
            int k4 = tid + j * TPB;                        // 0..2047
            int g  = bb * BOUT + 4 * k4;                   // >= 0 always
            float4 v;
            if (g + 3 < n) {
                v = *(const float4*)(r + g);
                vs += (v.x + v.y) + (v.z + v.w);
                vq += (v.x * v.x + v.y * v.y) + (v.z * v.z + v.w * v.w);
            } else {
                float* pv = (float*)&v;
                #pragma unroll
                for (int e = 0; e < 4; ++e) {
                    int t = g + e;
                    float x = (t < n) ? r[t] : 0.0f;
                    pv[e] = x;
                    if (t < n) { vs += x; vq = fmaf(x, x, vq); }
                }
            }
            *(float4*)(sbuf + HALO + 4 * k4) = v;
        }
        if (tid < HALO / 4) {                              // halo (no variance)
            int g = bb * BOUT - HALO + 4 * tid;
            float4 v;
            if (g >= 0 && g + 3 < n) {
                v = *(const float4*)(r + g);
            } else {
                float* pv = (float*)&v;
                #pragma unroll
                for (int e = 0; e < 4; ++e) {
                    int t = g + e;
                    pv[e] = (t >= 0 && t < n) ? r[t] : 0.0f;
                }
            }
            *(float4*)(sbuf + 4 * tid) = v;
        }
        __syncthreads();

        // ---- Phase 2: per-warp segmented scan from smem ----
        float c_prev = 0.0f;
        #pragma unroll
        for (int s = 0; s < TSEG; ++s) {
            const int  L     = wid * WSPAN + s * 256;      // local segment base
            const int  li    = L + 8 * lane;               // this lane's base
            const int  t0    = base_t + li;                // global index
            const bool isout = (s >= 1);
            const int  tseg  = base_t + L;
            const bool fast  = (tseg >= 1) && (tseg + 256 <= n);

            float  pm1 = sbuf[(li >= 1) ? (li - 1) : 0];   // r[t0-1]
            float4 A   = *(const float4*)(sbuf + li);
            float4 B   = *(const float4*)(sbuf + li + 4);

            float d0 = fmaf(alpha, pm1 * pm1, omega);
            float d1 = fmaf(alpha, A.x * A.x, omega);
            float d2 = fmaf(alpha, A.y * A.y, omega);
            float d3 = fmaf(alpha, A.z * A.z, omega);
            float d4 = fmaf(alpha, A.w * A.w, omega);
            float d5 = fmaf(alpha, B.x * B.x, omega);
            float d6 = fmaf(alpha, B.y * B.y, omega);
            float d7 = fmaf(alpha, B.z * B.z, omega);

            if (!fast) {                                   // zero invalid drivers
                if (t0 + 0 < 1 || t0 + 0 >= n) d0 = 0.0f;
                if (t0 + 1 < 1 || t0 + 1 >= n) d1 = 0.0f;
                if (t0 + 2 < 1 || t0 + 2 >= n) d2 = 0.0f;
                if (t0 + 3 < 1 || t0 + 3 >= n) d3 = 0.0f;
                if (t0 + 4 < 1 || t0 + 4 >= n) d4 = 0.0f;
                if (t0 + 5 < 1 || t0 + 5 >= n) d5 = 0.0f;
                if (t0 + 6 < 1 || t0 + 6 >= n) d6 = 0.0f;
                if (t0 + 7 < 1 || t0 + 7 >= n) d7 = 0.0f;
            }

            // local 8-chain end (zero entering state)
            float c = d0;
            c = fmaf(beta, c, d1); c = fmaf(beta, c, d2);
            c = fmaf(beta, c, d3); c = fmaf(beta, c, d4);
            c = fmaf(beta, c, d5); c = fmaf(beta, c, d6);
            c = fmaf(beta, c, d7);

            // Kogge-Stone: S_l = E_l + beta^8 * S_{l-1}
            float S = c, u;
            u = __shfl_up_sync(FULL, S, 1);  S = fmaf(M0, (lane >= 1)  ? u : 0.0f, S);
            u = __shfl_up_sync(FULL, S, 2);  S = fmaf(M1, (lane >= 2)  ? u : 0.0f, S);
            u = __shfl_up_sync(FULL, S, 4);  S = fmaf(M2, (lane >= 4)  ? u : 0.0f, S);
            u = __shfl_up_sync(FULL, S, 8);  S = fmaf(M3, (lane >= 8)  ? u : 0.0f, S);
            u = __shfl_up_sync(FULL, S, 16); S = fmaf(M4, (lane >= 16) ? u : 0.0f, S);

            float c_next = __shfl_sync(FULL, S, 31);       // beta^256*c_prev dropped
            float Sp     = __shfl_up_sync(FULL, S, 1);

            if (isout) {
                float G  = fmaf(lanepow, c_prev, (lane >= 1) ? Sp : 0.0f);
                float h0 = fmaf(beta, G,  d0);
                float h1 = fmaf(beta, h0, d1);
                float h2 = fmaf(beta, h1, d2);
                float h3 = fmaf(beta, h2, d3);
                float h4 = fmaf(beta, h3, d4);
                float h5 = fmaf(beta, h4, d5);
                float h6 = fmaf(beta, h5, d6);
                float h7 = fmaf(beta, h6, d7);

                if (t0 + 8 <= n) {                         // t0 >= 0 when isout
                    *(float4*)(out + t0)     = make_float4(fsqrt_ap(h0), fsqrt_ap(h1),
                                                           fsqrt_ap(h2), fsqrt_ap(h3));
                    *(float4*)(out + t0 + 4) = make_float4(fsqrt_ap(h4), fsqrt_ap(h5),
                                                           fsqrt_ap(h6), fsqrt_ap(h7));
                    if (wh4) {
                        *(float4*)(out + n + t0)     = make_float4(h0, h1, h2, h3);
                        *(float4*)(out + n + t0 + 4) = make_float4(h4, h5, h6, h7);
                    } else if (wh) {
                        float hv[8] = {h0, h1, h2, h3, h4, h5, h6, h7};
                        #pragma unroll
                        for (int e = 0; e < 8; ++e) out[n + t0 + e] = hv[e];
                    }
                } else {
                    float hv[8] = {h0, h1, h2, h3, h4, h5, h6, h7};
                    #pragma unroll
                    for (int e = 0; e < 8; ++e) {
                        int t = t0 + e;
                        if (t >= 0 && t < n) {
                            out[t] = fsqrt_ap(hv[e]);
                            if (wh) out[n + t] = hv[e];
                        }
                    }
                }
            }
            c_prev = c_next;
        }
        __syncthreads();                                   // sbuf reuse (multi-tile)
    }

    // ---- per-block deterministic variance partial ----
    #pragma unroll
    for (int off = 16; off; off >>= 1) {
        vs += __shfl_down_sync(FULL, vs, off);
        vq += __shfl_down_sync(FULL, vq, off);
    }
    if (lane == 0) { swsum[wid] = vs; swq[wid] = vq; }
    __syncthreads();
    if (tid == 0) {
        double a = 0.0, q = 0.0;
        #pragma unroll
        for (int w = 0; w < WARPS; ++w) { a += (double)swsum[w]; q += (double)swq[w]; }
        g_psum[blockIdx.x]   = a;
        g_psumsq[blockIdx.x] = q;
        __threadfence();                                   // release (cumulative
        s_ticket = atomicAdd(&g_ticket, 1u);               //  after syncthreads)
    }
    __syncthreads();
    if (s_ticket != (unsigned)(gridDim.x - 1)) return;

    // ---- last block: reduce partials, patch h0 term ----
    if (tid == 0) g_ticket = 0;                            // reset for replays
    __threadfence();                                       // acquire side

    double* red  = (double*)sbuf;                          // reuse staging buffer
    double* red2 = red + TPB;
    {
        double a = 0.0, q = 0.0;
        for (int i = tid; i < (int)gridDim.x; i += TPB) { a += g_psum[i]; q += g_psumsq[i]; }
        red[tid] = a; red2[tid] = q;
    }
    __syncthreads();
    for (int s = TPB / 2; s; s >>= 1) {
        if (tid < s) { red[tid] += red[tid + s]; red2[tid] += red2[tid + s]; }
        __syncthreads();
    }
    if (tid == 0) {
        double Ssum = red[0], Q = red2[0];
        sh0 = (float)((Q - Ssum * Ssum / (double)n) / (double)(n - 1));
    }
    __syncthreads();

    const float h0v = sh0;
    const int   lim = (FIXN < n) ? FIXN : n;
    if (wh) {
        // h[t] = h_hat[t] + beta^t * h0; h_hat already in out[n+t]
        for (int t = tid; t < lim; t += TPB) {
            float pw2 = 1.0f, bb2 = beta; int e = t;
            while (e) { if (e & 1) pw2 *= bb2; bb2 *= bb2; e >>= 1; }
            float hh = (t == 0) ? h0v : fmaf(pw2, h0v, out[n + t]);
            out[n + t] = hh;
            out[t] = fsqrt_ap(hh);
        }
    } else {
        if (tid == 0) {                                    // fallback: serial prefix
            float h = h0v;
            out[0] = fsqrt_ap(h);
            for (int t = 1; t < lim; ++t) {
                float rv = r[t - 1];
                h = fmaf(beta, h, fmaf(alpha * rv, rv, omega));
                out[t] = fsqrt_ap(h);
            }
        }
    }
}

extern "C" void kernel_launch(void* const* d_in, const int* in_sizes, int n_in,
                              void* d_out, int out_size)
{
    const float* r  = (const float*)d_in[0];
    const float* om = (const float*)d_in[1];
    const float* al = (const float*)d_in[2];
    const float* be = (const float*)d_in[3];
    float* out = (float*)d_out;

    const int n = in_sizes[0];
    const int write_h = (out_size >= 2 * n) ? 1 : 0;

    int ntiles = (n + BOUT - 1) / BOUT;
    if (ntiles < 1) ntiles = 1;
    int grid = (ntiles < MAXB) ? ntiles : MAXB;

    garch_fused<<<grid, TPB>>>(r, om, al, be, out, n, ntiles, write_h);
}

// round 8
// speedup vs baseline: 1.4111x; 1.4111x over previous
#include <cuda_runtime.h>

// GARCH(1,1): h[t] = (omega + alpha*r[t-1]^2) + beta*h[t-1], h[0] = var(r, ddof=1)
// out[0..n) = sqrt(h), out[n..2n) = h
//
// Reverted to the measured-fastest design (R2: padded-smem Hillis-Steele),
// with exactly two changes: sqrt.approx in the main kernel, and MLP-optimized
// loads in the fixup kernel. beta<1 => contractive recurrence (beta^256 ~
// 8e-19 < fp32 ulp): blocks process independent tiles with a 256-elem warm-up
// halo; the intra-block stitch is EXACT. Main computes the zero-state solution
// h_hat; true h[t] = h_hat[t] + beta^t*h0 (linearity), patched for t<256 by
// the fixup kernel, which also reduces the fp32 variance partials.

#define TPB   256
#define CPT   32
#define TILE  (TPB*CPT)        // 8192
#define HALO  256
#define OPB   (TILE - HALO)    // 7936
#define FIXN  256
#define MAXB  4096

__device__ double g_psum[MAXB];
__device__ double g_psumsq[MAXB];

__device__ __forceinline__ int padidx(int k) { return k + (k >> 5); }

__device__ __forceinline__ float fsqrt_ap(float x) {
    float y; asm("sqrt.approx.f32 %0, %1;" : "=f"(y) : "f"(x)); return y;
}

__global__ void __launch_bounds__(TPB)
garch_main(const float* __restrict__ r,
           const float* __restrict__ omega_p,
           const float* __restrict__ alpha_p,
           const float* __restrict__ beta_p,
           float* __restrict__ out,
           int n, int write_h)
{
    __shared__ float  bpad[TILE + TILE/32];
    __shared__ float  sscan[TPB];
    __shared__ double wsum[TPB/32], wsq[TPB/32];

    const int   tid   = threadIdx.x;
    const float omega = *omega_p;
    const float alpha = *alpha_p;
    const float beta  = *beta_p;

    const long long tile_t0 = (long long)blockIdx.x * OPB + 1 - HALO;
    const long long s0      = tile_t0 - 1;              // r index for k=0

    float vs = 0.0f, vq = 0.0f;                          // fp32 variance partials

    // ---- Phase 1: load r, compute drivers b[t] = omega + alpha*r[t-1]^2 ----
    const bool interior = (s0 >= 0) && (s0 + TILE < (long long)n);
    if (interior) {
        const float4* __restrict__ r4 = (const float4*)(r + s0);   // 16B aligned
        #pragma unroll
        for (int it = 0; it < TILE / (4 * TPB); ++it) {
            int q = tid + it * TPB;
            float4 v = r4[q];
            int k = 4 * q;
            int base = padidx(k);                        // k%4==0: no pad break
            bpad[base + 0] = fmaf(alpha * v.x, v.x, omega);
            bpad[base + 1] = fmaf(alpha * v.y, v.y, omega);
            bpad[base + 2] = fmaf(alpha * v.z, v.z, omega);
            bpad[base + 3] = fmaf(alpha * v.w, v.w, omega);
            if (k >= HALO) {                             // exclusive region
                vs += (v.x + v.y) + (v.z + v.w);
                vq += fmaf(v.x, v.x, v.y * v.y) + fmaf(v.z, v.z, v.w * v.w);
            }
        }
    } else {
        #pragma unroll
        for (int it = 0; it < TILE / TPB; ++it) {
            int k = tid + it * TPB;
            long long t = tile_t0 + k;
            float b = 0.0f;
            if (t >= 1 && t < (long long)n) {
                float rv = r[t - 1];
                b = fmaf(alpha * rv, rv, omega);
                if (k >= HALO) { vs += rv; vq = fmaf(rv, rv, vq); }
            }
            bpad[padidx(k)] = b;
        }
    }
    if (blockIdx.x == 0 && tid == 0) {                   // r[n-1]: never a driver
        float rv = r[n - 1];
        vs += rv; vq = fmaf(rv, rv, vq);
    }
    __syncthreads();

    // ---- Phase 2: per-thread serial recurrence from zero state ----
    float p[CPT];
    {
        float h = 0.0f;
        const int base = padidx(tid * CPT);              // tid*33: conflict-free
        #pragma unroll
        for (int j = 0; j < CPT; ++j) {
            h = fmaf(beta, h, bpad[base + j]);
            p[j] = h;
        }
        sscan[tid] = h;
    }
    __syncthreads();

    // ---- Phase 3: exact stitch S_i = E_i + beta^32 * S_{i-1} ----
    float b2 = beta * beta, b4 = b2 * b2, b8 = b4 * b4, b16 = b8 * b8;
    float m = b16 * b16;                                 // beta^32
    for (int d = 1; d < TPB; d <<= 1) {
        float v  = sscan[tid];
        float lo = (tid >= d) ? sscan[tid - d] : 0.0f;
        __syncthreads();
        v = fmaf(m, lo, v);
        sscan[tid] = v;
        __syncthreads();
        m *= m;
    }
    float carry = (tid >= 1) ? sscan[tid - 1] : 0.0f;

    // ---- Phase 4: apply carry, stage h in shared ----
    {
        const int base = padidx(tid * CPT);
        float bp = beta;
        #pragma unroll
        for (int j = 0; j < CPT; ++j) {
            float h = fmaf(bp, carry, p[j]);
            bpad[base + j] = h;
            bp *= beta;
        }
    }
    __syncthreads();

    // ---- Phase 5: coalesced stores of sqrt(h) and h ----
    #pragma unroll
    for (int it = 0; it < TILE / TPB; ++it) {
        int k = tid + it * TPB;
        if (k < HALO) continue;
        long long t = tile_t0 + k;
        if (t < (long long)n) {
            float h = bpad[padidx(k)];
            out[t] = fsqrt_ap(h);
            if (write_h) out[(long long)n + t] = h;
        }
    }

    // ---- Phase 6: deterministic variance reduce (fp32 -> fp64 at warp level) ----
    unsigned mask = 0xFFFFFFFFu;
    #pragma unroll
    for (int off = 16; off; off >>= 1) {
        vs += __shfl_down_sync(mask, vs, off);
        vq += __shfl_down_sync(mask, vq, off);
    }
    const int wid = tid >> 5, lane = tid & 31;
    if (lane == 0) { wsum[wid] = (double)vs; wsq[wid] = (double)vq; }
    __syncthreads();
    if (tid == 0) {
        double a = 0.0, b_ = 0.0;
        #pragma unroll
        for (int w = 0; w < TPB / 32; ++w) { a += wsum[w]; b_ += wsq[w]; }
        g_psum[blockIdx.x]   = a;
        g_psumsq[blockIdx.x] = b_;
    }
}

__global__ void __launch_bounds__(TPB)
garch_fixup(const float* __restrict__ r,
            const float* __restrict__ omega_p,
            const float* __restrict__ alpha_p,
            const float* __restrict__ beta_p,
            float* __restrict__ out,
            int n, int nblocks, int write_h)
{
    __shared__ double red[TPB], red2[TPB];
    __shared__ float  sh0;
    const int tid = threadIdx.x;

    // hoist independent loads up front (hide DRAM latency under reduction)
    const float beta = *beta_p;
    const int   lim  = (FIXN < n) ? FIXN : n;
    float hhat = 0.0f;
    if (write_h && tid < lim) hhat = out[n + tid];       // prefetch h_hat[t]

    // deterministic reduction of per-block partials, 4-way MLP
    {
        double a0 = 0.0, a1 = 0.0, a2 = 0.0, a3 = 0.0;
        double q0 = 0.0, q1 = 0.0, q2 = 0.0, q3 = 0.0;
        int i = tid;
        for (; i + 3 * TPB < nblocks; i += 4 * TPB) {
            a0 += g_psum[i];           q0 += g_psumsq[i];
            a1 += g_psum[i + TPB];     q1 += g_psumsq[i + TPB];
            a2 += g_psum[i + 2*TPB];   q2 += g_psumsq[i + 2*TPB];
            a3 += g_psum[i + 3*TPB];   q3 += g_psumsq[i + 3*TPB];
        }
        for (; i < nblocks; i += TPB) { a0 += g_psum[i]; q0 += g_psumsq[i]; }
        red[tid]  = (a0 + a1) + (a2 + a3);
        red2[tid] = (q0 + q1) + (q2 + q3);
    }
    __syncthreads();
    for (int s = TPB / 2; s; s >>= 1) {
        if (tid < s) { red[tid] += red[tid + s]; red2[tid] += red2[tid + s]; }
        __syncthreads();
    }
    if (tid == 0) {
        double S = red[0], Q = red2[0];
        sh0 = (float)((Q - S * S / (double)n) / (double)(n - 1));
    }
    __syncthreads();

    const float h0 = sh0;
    if (write_h) {
        // h[t] = h_hat[t] + beta^t * h0 (linearity); lim <= TPB so one pass
        if (tid < lim) {
            int t = tid;
            float bp = 1.0f, base = beta;
            int e = t;
            while (e) { if (e & 1) bp *= base; base *= base; e >>= 1; }
            float hh = (t == 0) ? h0 : fmaf(bp, h0, hhat);
            out[n + t] = hh;
            out[t] = fsqrt_ap(hh);
        }
    } else {
        if (tid == 0) {                                  // rare fallback
            float omega = *omega_p, alpha = *alpha_p;
            float h = h0;
            out[0] = fsqrt_ap(h);
            for (int t = 1; t < lim; ++t) {
                float rv = r[t - 1];
                h = fmaf(beta, h, fmaf(alpha * rv, rv, omega));
                out[t] = fsqrt_ap(h);
            }
        }
    }
}

extern "C" void kernel_launch(void* const* d_in, const int* in_sizes, int n_in,
                              void* d_out, int out_size)
{
    const float* r  = (const float*)d_in[0];
    const float* om = (const float*)d_in[1];
    const float* al = (const float*)d_in[2];
    const float* be = (const float*)d_in[3];
    float* out = (float*)d_out;

    const int n = in_sizes[0];
    const int write_h = (out_size >= 2 * n) ? 1 : 0;

    int nblocks = (n - 1 + OPB - 1) / OPB;
    if (nblocks < 1)    nblocks = 1;
    if (nblocks > MAXB) nblocks = MAXB;

    garch_main <<<nblocks, TPB>>>(r, om, al, be, out, n, write_h);
    garch_fixup<<<1,       TPB>>>(r, om, al, be, out, n, nblocks, write_h);
}